// round 4
// baseline (speedup 1.0000x reference)
#include <cuda_runtime.h>
#include <cuda_fp16.h>
#include <cstdint>

#define B_ 4
#define N_ 4096
#define F_ 64
#define BM 128
#define BK 32
#define NKT (N_ / BK)                       // 128

// smem stage layout (all fp16, 64B rows, XOR-swizzled 16B chunks)
#define A_CH_BYTES (BM * 64)                // 8192 per chain
#define T_CH_BYTES (F_ * 64)                // 4096 per chain
#define A_BYTES (3 * A_CH_BYTES)            // 24576
#define STAGE_BYTES (A_BYTES + 3 * T_CH_BYTES)  // 36864
#define SMEM_BYTES (3 * STAGE_BYTES)        // 110592

// T scratch: g_T[c][b][n][k] = fp16_rne( (X[b] @ w_c)[k][n] )  (B operand, n-major)
__device__ __half g_T[3][B_][F_][N_];

// ---------------------------------------------------------------------------
__device__ __forceinline__ uint32_t smem_u32(const void* p) {
    uint32_t a;
    asm("{ .reg .u64 t; cvta.to.shared.u64 t, %1; cvt.u32.u64 %0, t; }"
        : "=r"(a) : "l"(p));
    return a;
}
__device__ __forceinline__ void ldsm4(uint32_t* r, uint32_t addr) {
    asm volatile("ldmatrix.sync.aligned.m8n8.x4.shared.b16 {%0,%1,%2,%3}, [%4];"
                 : "=r"(r[0]), "=r"(r[1]), "=r"(r[2]), "=r"(r[3]) : "r"(addr));
}
__device__ __forceinline__ void mma16816(float* d, const uint32_t* a,
                                         uint32_t b0, uint32_t b1) {
    asm volatile("mma.sync.aligned.m16n8k16.row.col.f32.f16.f16.f32 "
                 "{%0,%1,%2,%3}, {%4,%5,%6,%7}, {%8,%9}, {%0,%1,%2,%3};"
                 : "+f"(d[0]), "+f"(d[1]), "+f"(d[2]), "+f"(d[3])
                 : "r"(a[0]), "r"(a[1]), "r"(a[2]), "r"(a[3]), "r"(b0), "r"(b1));
}
__device__ __forceinline__ uint32_t packh2(float x, float y) {
    __half2 h = __floats2half2_rn(x, y);
    return *(uint32_t*)&h;
}

// ---------------------------------------------------------------------------
// Kernel 1: g_T[c][b][g][m] = fp16( sum_f X[b][m][f] * w_c[f][g] )
// ---------------------------------------------------------------------------
__global__ void __launch_bounds__(256)
compute_T_kernel(const float* __restrict__ X,
                 const float* __restrict__ w0,
                 const float* __restrict__ w1,
                 const float* __restrict__ w2) {
    const int c = blockIdx.z;
    const int b = blockIdx.y;
    const int m0 = blockIdx.x * 64;
    const float* w = (c == 0) ? w0 : (c == 1) ? w1 : w2;

    __shared__ float sX[64 * 68];
    __shared__ float sW[64 * 68];

    const int tid = threadIdx.x;
    {
        const int q = tid & 15;
        const int r = tid >> 4;
        #pragma unroll
        for (int j = 0; j < 4; j++) {
            const int row = r + 16 * j;
            *(float4*)(sX + row * 68 + q * 4) =
                *(const float4*)(X + ((size_t)b * N_ + m0 + row) * F_ + q * 4);
            *(float4*)(sW + row * 68 + q * 4) =
                *(const float4*)(w + (size_t)row * F_ + q * 4);
        }
    }
    __syncthreads();

    const int row = tid >> 2;
    const int g0  = (tid & 3) * 16;

    float acc[16];
    #pragma unroll
    for (int i = 0; i < 16; i++) acc[i] = 0.f;

    #pragma unroll 8
    for (int f = 0; f < 64; f++) {
        const float x = sX[row * 68 + f];
        #pragma unroll
        for (int j = 0; j < 4; j++) {
            float4 wv = *(const float4*)(sW + f * 68 + g0 + j * 4);
            acc[j * 4 + 0] += x * wv.x;
            acc[j * 4 + 1] += x * wv.y;
            acc[j * 4 + 2] += x * wv.z;
            acc[j * 4 + 3] += x * wv.w;
        }
    }
    __syncthreads();

    #pragma unroll
    for (int j = 0; j < 4; j++)
        *(float4*)(sX + row * 68 + g0 + j * 4) =
            make_float4(acc[j*4+0], acc[j*4+1], acc[j*4+2], acc[j*4+3]);
    __syncthreads();

    // transposed fp16 write: thread handles column g, 16 consecutive m's (32B)
    const int g  = tid >> 2;
    const int ms = (tid & 3) * 16;
    uint32_t h[8];
    #pragma unroll
    for (int i = 0; i < 8; i++)
        h[i] = packh2(sX[(ms + 2*i) * 68 + g], sX[(ms + 2*i + 1) * 68 + g]);
    __half* out = &g_T[c][b][g][m0 + ms];
    ((uint4*)out)[0] = make_uint4(h[0], h[1], h[2], h[3]);
    ((uint4*)out)[1] = make_uint4(h[4], h[5], h[6], h[7]);
}

// ---------------------------------------------------------------------------
// Kernel 2: Y[b] = relu(A0@T0 + A1@T1 + A2@T2), fp16 mma, 3-stage ring
// grid (32, 4), block 256 (8 warps: 4M x 2N over 128x64)
// ---------------------------------------------------------------------------
__global__ void __launch_bounds__(256, 1)
gnn_main_kernel(const float* __restrict__ A0,
                const float* __restrict__ A1,
                const float* __restrict__ A2,
                float* __restrict__ Y) {
    extern __shared__ char smem[];
    const uint32_t sb = smem_u32(smem);
    const int tid = threadIdx.x;
    const int b = blockIdx.y;
    const int rowBase = blockIdx.x * BM;

    const float* Ap[3];
    Ap[0] = A0 + (size_t)b * N_ * N_;
    Ap[1] = A1 + (size_t)b * N_ * N_;
    Ap[2] = A2 + (size_t)b * N_ * N_;

    // A staging: 6 x (2x LDG.128 fp32 -> cvt -> 16B STS) per thread
    const float* aSrc[6];
    uint32_t aDst[6];
    #pragma unroll
    for (int j = 0; j < 6; j++) {
        const int id  = tid + 256 * j;            // 0..1535
        const int c   = id >> 9;
        const int rem = id & 511;
        const int q2  = rem >> 7;                 // 16B chunk (8 k's)
        const int row = rem & 127;
        aSrc[j] = Ap[c] + (size_t)(rowBase + row) * N_ + q2 * 8;
        aDst[j] = (uint32_t)(c * A_CH_BYTES + row * 64
                             + 16 * (q2 ^ ((row >> 1) & 3)));
    }
    // T staging: 3 x 16B cp.async per thread
    const __half* tSrc[3];
    uint32_t tDst[3];
    #pragma unroll
    for (int j = 0; j < 3; j++) {
        const int id  = tid + 256 * j;            // 0..767
        const int c   = id >> 8;
        const int rem = id & 255;
        const int n   = rem >> 2;
        const int ch  = rem & 3;
        tSrc[j] = &g_T[c][b][n][0] + ch * 8;
        tDst[j] = (uint32_t)(A_BYTES + c * T_CH_BYTES + n * 64
                             + 16 * (ch ^ ((n >> 1) & 3)));
    }

    float4 rA[12];
    #define LDG_A(kt) do {                                                     \
        const int _k0 = (kt) * BK;                                             \
        _Pragma("unroll")                                                      \
        for (int j = 0; j < 6; j++) {                                          \
            rA[2*j]   = __ldcg((const float4*)(aSrc[j] + _k0));                \
            rA[2*j+1] = __ldcg((const float4*)(aSrc[j] + _k0 + 4));            \
        }                                                                      \
    } while (0)

    #define STS_A(stage) do {                                                  \
        char* _p = smem + (stage) * STAGE_BYTES;                               \
        _Pragma("unroll")                                                      \
        for (int j = 0; j < 6; j++) {                                          \
            float4 v0 = rA[2*j], v1 = rA[2*j+1];                               \
            *(uint4*)(_p + aDst[j]) = make_uint4(                              \
                packh2(v0.x, v0.y), packh2(v0.z, v0.w),                        \
                packh2(v1.x, v1.y), packh2(v1.z, v1.w));                       \
        }                                                                      \
    } while (0)

    #define CP_T(kt, stage) do {                                              \
        const uint32_t _so = sb + (stage) * STAGE_BYTES;                       \
        const int _k0 = (kt) * BK;                                             \
        _Pragma("unroll")                                                      \
        for (int j = 0; j < 3; j++)                                            \
            asm volatile("cp.async.cg.shared.global [%0], [%1], 16;"           \
                         :: "r"(_so + tDst[j]), "l"(tSrc[j] + _k0) : "memory");\
        asm volatile("cp.async.commit_group;" ::: "memory");                   \
    } while (0)

    // fragment geometry
    const int lane  = tid & 31;
    const int warp  = tid >> 5;
    const int warpM = warp >> 1;       // 0..3 -> 32 rows each
    const int warpN = warp & 1;        // 0..1 -> 32 cols each
    const int row16 = lane & 15;
    const int cbit  = lane >> 4;       // k-chunk half selector for ldmatrix
    const uint32_t swz = (uint32_t)((row16 >> 1) & 3);
    const uint32_t aRowOff = (uint32_t)((warpM * 32 + row16) * 64);
    const uint32_t bRowOff = (uint32_t)(A_BYTES + (warpN * 32 + row16) * 64);

    float acc[2][4][4];
    #pragma unroll
    for (int mt = 0; mt < 2; mt++)
        #pragma unroll
        for (int nt = 0; nt < 4; nt++)
            #pragma unroll
            for (int i = 0; i < 4; i++) acc[mt][nt][i] = 0.f;

    // prologue: stages 0,1 in flight; A(2) in registers
    LDG_A(0); STS_A(0); CP_T(0, 0);
    LDG_A(1); STS_A(1); CP_T(1, 1);
    LDG_A(2);

    for (int s = 0; s < NKT; s++) {
        const int slot = s % 3;
        asm volatile("cp.async.wait_group 1;" ::: "memory");
        __syncthreads();

        // refill stage s+2 (slot (s+2)%3, freed by iter s-1's reads)
        if (s + 2 < NKT) {
            const int ns = (s + 2) % 3;
            STS_A(ns);
            CP_T(s + 2, ns);
        } else {
            asm volatile("cp.async.commit_group;" ::: "memory");  // keep count uniform
        }
        if (s + 3 < NKT) LDG_A(s + 3);

        // compute on stage s
        const uint32_t stBase = sb + (uint32_t)slot * STAGE_BYTES;
        #pragma unroll
        for (int c = 0; c < 3; c++) {
            const uint32_t aCh = stBase + c * A_CH_BYTES + aRowOff;
            const uint32_t bCh = stBase + c * T_CH_BYTES + bRowOff;
            #pragma unroll
            for (int ks = 0; ks < 2; ks++) {
                const uint32_t kch = 16u * ((uint32_t)((ks << 1) | cbit) ^ swz);
                uint32_t a0[4], a1[4], b0[4], b1[4];
                ldsm4(a0, aCh + kch);              // m rows 0-15 of warp tile
                ldsm4(a1, aCh + 1024 + kch);       // m rows 16-31
                ldsm4(b0, bCh + kch);              // n 0-15 of warp tile
                ldsm4(b1, bCh + 1024 + kch);       // n 16-31
                mma16816(acc[0][0], a0, b0[0], b0[2]);
                mma16816(acc[1][0], a1, b0[0], b0[2]);
                mma16816(acc[0][1], a0, b0[1], b0[3]);
                mma16816(acc[1][1], a1, b0[1], b0[3]);
                mma16816(acc[0][2], a0, b1[0], b1[2]);
                mma16816(acc[1][2], a1, b1[0], b1[2]);
                mma16816(acc[0][3], a0, b1[1], b1[3]);
                mma16816(acc[1][3], a1, b1[1], b1[3]);
            }
        }
    }

    // epilogue: relu + store
    #pragma unroll
    for (int mt = 0; mt < 2; mt++) {
        #pragma unroll
        for (int nt = 0; nt < 4; nt++) {
            const int r0  = rowBase + warpM * 32 + mt * 16 + (lane >> 2);
            const int col = warpN * 32 + nt * 8 + (lane & 3) * 2;
            float2 v0 = make_float2(fmaxf(acc[mt][nt][0], 0.f),
                                    fmaxf(acc[mt][nt][1], 0.f));
            float2 v1 = make_float2(fmaxf(acc[mt][nt][2], 0.f),
                                    fmaxf(acc[mt][nt][3], 0.f));
            *(float2*)(Y + ((size_t)b * N_ + r0) * F_ + col)     = v0;
            *(float2*)(Y + ((size_t)b * N_ + r0 + 8) * F_ + col) = v1;
        }
    }
}

// ---------------------------------------------------------------------------
extern "C" void kernel_launch(void* const* d_in, const int* in_sizes, int n_in,
                              void* d_out, int out_size) {
    (void)in_sizes; (void)n_in; (void)out_size;
    const float* X  = (const float*)d_in[0];
    const float* A0 = (const float*)d_in[1];
    const float* A1 = (const float*)d_in[2];
    const float* A2 = (const float*)d_in[3];
    const float* w0 = (const float*)d_in[4];
    const float* w1 = (const float*)d_in[5];
    const float* w2 = (const float*)d_in[6];
    float* Y = (float*)d_out;

    dim3 g1(N_ / 64, B_, 3);
    compute_T_kernel<<<g1, 256>>>(X, w0, w1, w2);

    cudaFuncSetAttribute(gnn_main_kernel,
                         cudaFuncAttributeMaxDynamicSharedMemorySize, SMEM_BYTES);
    dim3 g2(N_ / BM, B_);
    gnn_main_kernel<<<g2, 256, SMEM_BYTES>>>(A0, A1, A2, Y);
}

// round 5
// speedup vs baseline: 1.1333x; 1.1333x over previous
#include <cuda_runtime.h>
#include <cuda_fp16.h>
#include <cstdint>

#define B_ 4
#define N_ 4096
#define F_ 64
#define BM 64
#define BK 32
#define NKT (N_ / BK)                       // 128
#define STAGES 4

// smem stage layout (fp16, 64B rows, XOR-swizzled 16B chunks)
#define A_CH_BYTES (BM * 64)                // 4096 per chain
#define T_CH_BYTES (F_ * 64)                // 4096 per chain
#define A_BYTES (3 * A_CH_BYTES)            // 12288
#define STAGE_BYTES (A_BYTES + 3 * T_CH_BYTES)  // 24576
#define SMEM_BYTES (STAGES * STAGE_BYTES)   // 98304 -> 2 CTAs/SM

// T scratch: g_T[c][b][n][k] = fp16_rne( (X[b] @ w_c)[k][n] )  (B operand, n-major)
__device__ __half g_T[3][B_][F_][N_];

// ---------------------------------------------------------------------------
__device__ __forceinline__ uint32_t smem_u32(const void* p) {
    uint32_t a;
    asm("{ .reg .u64 t; cvta.to.shared.u64 t, %1; cvt.u32.u64 %0, t; }"
        : "=r"(a) : "l"(p));
    return a;
}
__device__ __forceinline__ void ldsm4(uint32_t* r, uint32_t addr) {
    asm volatile("ldmatrix.sync.aligned.m8n8.x4.shared.b16 {%0,%1,%2,%3}, [%4];"
                 : "=r"(r[0]), "=r"(r[1]), "=r"(r[2]), "=r"(r[3]) : "r"(addr));
}
__device__ __forceinline__ void mma16816(float* d, const uint32_t* a,
                                         uint32_t b0, uint32_t b1) {
    asm volatile("mma.sync.aligned.m16n8k16.row.col.f32.f16.f16.f32 "
                 "{%0,%1,%2,%3}, {%4,%5,%6,%7}, {%8,%9}, {%0,%1,%2,%3};"
                 : "+f"(d[0]), "+f"(d[1]), "+f"(d[2]), "+f"(d[3])
                 : "r"(a[0]), "r"(a[1]), "r"(a[2]), "r"(a[3]), "r"(b0), "r"(b1));
}
__device__ __forceinline__ uint32_t packh2(float x, float y) {
    __half2 h = __floats2half2_rn(x, y);
    return *(uint32_t*)&h;
}

// ---------------------------------------------------------------------------
// Kernel 1: g_T[c][b][g][m] = fp16( sum_f X[b][m][f] * w_c[f][g] )
// ---------------------------------------------------------------------------
__global__ void __launch_bounds__(256)
compute_T_kernel(const float* __restrict__ X,
                 const float* __restrict__ w0,
                 const float* __restrict__ w1,
                 const float* __restrict__ w2) {
    const int c = blockIdx.z;
    const int b = blockIdx.y;
    const int m0 = blockIdx.x * 64;
    const float* w = (c == 0) ? w0 : (c == 1) ? w1 : w2;

    __shared__ float sX[64 * 68];
    __shared__ float sW[64 * 68];

    const int tid = threadIdx.x;
    {
        const int q = tid & 15;
        const int r = tid >> 4;
        #pragma unroll
        for (int j = 0; j < 4; j++) {
            const int row = r + 16 * j;
            *(float4*)(sX + row * 68 + q * 4) =
                *(const float4*)(X + ((size_t)b * N_ + m0 + row) * F_ + q * 4);
            *(float4*)(sW + row * 68 + q * 4) =
                *(const float4*)(w + (size_t)row * F_ + q * 4);
        }
    }
    __syncthreads();

    const int row = tid >> 2;
    const int g0  = (tid & 3) * 16;

    float acc[16];
    #pragma unroll
    for (int i = 0; i < 16; i++) acc[i] = 0.f;

    #pragma unroll 8
    for (int f = 0; f < 64; f++) {
        const float x = sX[row * 68 + f];
        #pragma unroll
        for (int j = 0; j < 4; j++) {
            float4 wv = *(const float4*)(sW + f * 68 + g0 + j * 4);
            acc[j * 4 + 0] += x * wv.x;
            acc[j * 4 + 1] += x * wv.y;
            acc[j * 4 + 2] += x * wv.z;
            acc[j * 4 + 3] += x * wv.w;
        }
    }
    __syncthreads();

    #pragma unroll
    for (int j = 0; j < 4; j++)
        *(float4*)(sX + row * 68 + g0 + j * 4) =
            make_float4(acc[j*4+0], acc[j*4+1], acc[j*4+2], acc[j*4+3]);
    __syncthreads();

    // transposed fp16 write: thread handles column g, 16 consecutive m's (32B)
    const int g  = tid >> 2;
    const int ms = (tid & 3) * 16;
    uint32_t h[8];
    #pragma unroll
    for (int i = 0; i < 8; i++)
        h[i] = packh2(sX[(ms + 2*i) * 68 + g], sX[(ms + 2*i + 1) * 68 + g]);
    __half* out = &g_T[c][b][g][m0 + ms];
    ((uint4*)out)[0] = make_uint4(h[0], h[1], h[2], h[3]);
    ((uint4*)out)[1] = make_uint4(h[4], h[5], h[6], h[7]);
}

// ---------------------------------------------------------------------------
// Kernel 2: Y[b] = relu(A0@T0 + A1@T1 + A2@T2), fp16 mma, 4-stage ring,
// grid (64, 4) = 256 CTAs, block 128 (4 warps: 2M x 2N over 64x64 tile),
// 2 CTAs/SM. Compute-first loop order.
// ---------------------------------------------------------------------------
__global__ void __launch_bounds__(128, 2)
gnn_main_kernel(const float* __restrict__ A0,
                const float* __restrict__ A1,
                const float* __restrict__ A2,
                float* __restrict__ Y) {
    extern __shared__ char smem[];
    const uint32_t sb = smem_u32(smem);
    const int tid = threadIdx.x;
    const int b = blockIdx.y;
    const int rowBase = blockIdx.x * BM;

    const float* Ap[3];
    Ap[0] = A0 + (size_t)b * N_ * N_;
    Ap[1] = A1 + (size_t)b * N_ * N_;
    Ap[2] = A2 + (size_t)b * N_ * N_;

    // A staging: 6 x (2x LDG.128 fp32 -> cvt -> 16B STS) per thread
    const float* aSrc[6];
    uint32_t aDst[6];
    #pragma unroll
    for (int j = 0; j < 6; j++) {
        const int id  = tid + 128 * j;            // 0..767
        const int c   = id >> 8;
        const int rem = id & 255;
        const int q2  = rem >> 6;                 // 16B chunk (8 k's)
        const int row = rem & 63;
        aSrc[j] = Ap[c] + (size_t)(rowBase + row) * N_ + q2 * 8;
        aDst[j] = (uint32_t)(c * A_CH_BYTES + row * 64
                             + 16 * (q2 ^ ((row >> 1) & 3)));
    }
    // T staging: 6 x 16B cp.async per thread
    const __half* tSrc[6];
    uint32_t tDst[6];
    #pragma unroll
    for (int j = 0; j < 6; j++) {
        const int id  = tid + 128 * j;            // 0..767
        const int c   = id >> 8;
        const int rem = id & 255;
        const int n   = rem >> 2;
        const int ch  = rem & 3;
        tSrc[j] = &g_T[c][b][n][0] + ch * 8;
        tDst[j] = (uint32_t)(A_BYTES + c * T_CH_BYTES + n * 64
                             + 16 * (ch ^ ((n >> 1) & 3)));
    }

    float4 rA[12];
    #define LDG_A(kt) do {                                                     \
        const int _k0 = (kt) * BK;                                             \
        _Pragma("unroll")                                                      \
        for (int j = 0; j < 6; j++) {                                          \
            rA[2*j]   = __ldcs((const float4*)(aSrc[j] + _k0));                \
            rA[2*j+1] = __ldcs((const float4*)(aSrc[j] + _k0 + 4));            \
        }                                                                      \
    } while (0)

    #define STS_A(stage) do {                                                  \
        char* _p = smem + (stage) * STAGE_BYTES;                               \
        _Pragma("unroll")                                                      \
        for (int j = 0; j < 6; j++) {                                          \
            float4 v0 = rA[2*j], v1 = rA[2*j+1];                               \
            *(uint4*)(_p + aDst[j]) = make_uint4(                              \
                packh2(v0.x, v0.y), packh2(v0.z, v0.w),                        \
                packh2(v1.x, v1.y), packh2(v1.z, v1.w));                       \
        }                                                                      \
    } while (0)

    #define CP_T(kt, stage) do {                                              \
        const uint32_t _so = sb + (stage) * STAGE_BYTES;                       \
        const int _k0 = (kt) * BK;                                             \
        _Pragma("unroll")                                                      \
        for (int j = 0; j < 6; j++)                                            \
            asm volatile("cp.async.cg.shared.global [%0], [%1], 16;"           \
                         :: "r"(_so + tDst[j]), "l"(tSrc[j] + _k0) : "memory");\
        asm volatile("cp.async.commit_group;" ::: "memory");                   \
    } while (0)

    // fragment geometry: 4 warps, warp tile 32x32
    const int lane  = tid & 31;
    const int warp  = tid >> 5;
    const int warpM = warp >> 1;       // 0..1 -> 32 rows each
    const int warpN = warp & 1;        // 0..1 -> 32 cols each
    const int row16 = lane & 15;
    const int cbit  = lane >> 4;       // k-chunk half selector
    const uint32_t swz = (uint32_t)((row16 >> 1) & 3);
    const uint32_t aRowOff = (uint32_t)((warpM * 32 + row16) * 64);
    const uint32_t bRowOff = (uint32_t)(A_BYTES + (warpN * 32 + row16) * 64);

    float acc[2][4][4];
    #pragma unroll
    for (int mt = 0; mt < 2; mt++)
        #pragma unroll
        for (int nt = 0; nt < 4; nt++)
            #pragma unroll
            for (int i = 0; i < 4; i++) acc[mt][nt][i] = 0.f;

    // prologue: stages 0..2 in flight; A(3) in registers
    LDG_A(0); STS_A(0); CP_T(0, 0);
    LDG_A(1); STS_A(1); CP_T(1, 1);
    LDG_A(2); STS_A(2); CP_T(2, 2);
    LDG_A(3);

    for (int s = 0; s < NKT; s++) {
        const int slot = s & 3;
        asm volatile("cp.async.wait_group 2;" ::: "memory");
        __syncthreads();

        // compute on stage s FIRST (hides the refill latency below)
        const uint32_t stBase = sb + (uint32_t)slot * STAGE_BYTES;
        #pragma unroll
        for (int c = 0; c < 3; c++) {
            const uint32_t aCh = stBase + c * A_CH_BYTES + aRowOff;
            const uint32_t bCh = stBase + c * T_CH_BYTES + bRowOff;
            #pragma unroll
            for (int ks = 0; ks < 2; ks++) {
                const uint32_t kch = 16u * ((uint32_t)((ks << 1) | cbit) ^ swz);
                uint32_t a0[4], a1[4], b0[4], b1[4];
                ldsm4(a0, aCh + kch);              // m rows 0-15 of warp tile
                ldsm4(a1, aCh + 1024 + kch);       // m rows 16-31
                ldsm4(b0, bCh + kch);              // n 0-15
                ldsm4(b1, bCh + 1024 + kch);       // n 16-31
                mma16816(acc[0][0], a0, b0[0], b0[2]);
                mma16816(acc[1][0], a1, b0[0], b0[2]);
                mma16816(acc[0][1], a0, b0[1], b0[3]);
                mma16816(acc[1][1], a1, b0[1], b0[3]);
                mma16816(acc[0][2], a0, b1[0], b1[2]);
                mma16816(acc[1][2], a1, b1[0], b1[2]);
                mma16816(acc[0][3], a0, b1[1], b1[3]);
                mma16816(acc[1][3], a1, b1[1], b1[3]);
            }
        }

        // refill stage s+3 (slot (s+3)&3 = (s-1)&3, freed by iter s-1)
        if (s + 3 < NKT) {
            const int ns = (s + 3) & 3;
            STS_A(ns);
            CP_T(s + 3, ns);
        } else {
            asm volatile("cp.async.commit_group;" ::: "memory");  // keep counts uniform
        }
        if (s + 4 < NKT) LDG_A(s + 4);
    }

    // epilogue: relu + store
    #pragma unroll
    for (int mt = 0; mt < 2; mt++) {
        #pragma unroll
        for (int nt = 0; nt < 4; nt++) {
            const int r0  = rowBase + warpM * 32 + mt * 16 + (lane >> 2);
            const int col = warpN * 32 + nt * 8 + (lane & 3) * 2;
            float2 v0 = make_float2(fmaxf(acc[mt][nt][0], 0.f),
                                    fmaxf(acc[mt][nt][1], 0.f));
            float2 v1 = make_float2(fmaxf(acc[mt][nt][2], 0.f),
                                    fmaxf(acc[mt][nt][3], 0.f));
            *(float2*)(Y + ((size_t)b * N_ + r0) * F_ + col)     = v0;
            *(float2*)(Y + ((size_t)b * N_ + r0 + 8) * F_ + col) = v1;
        }
    }
}

// ---------------------------------------------------------------------------
extern "C" void kernel_launch(void* const* d_in, const int* in_sizes, int n_in,
                              void* d_out, int out_size) {
    (void)in_sizes; (void)n_in; (void)out_size;
    const float* X  = (const float*)d_in[0];
    const float* A0 = (const float*)d_in[1];
    const float* A1 = (const float*)d_in[2];
    const float* A2 = (const float*)d_in[3];
    const float* w0 = (const float*)d_in[4];
    const float* w1 = (const float*)d_in[5];
    const float* w2 = (const float*)d_in[6];
    float* Y = (float*)d_out;

    dim3 g1(N_ / 64, B_, 3);
    compute_T_kernel<<<g1, 256>>>(X, w0, w1, w2);

    cudaFuncSetAttribute(gnn_main_kernel,
                         cudaFuncAttributeMaxDynamicSharedMemorySize, SMEM_BYTES);
    dim3 g2(N_ / BM, B_);
    gnn_main_kernel<<<g2, 128, SMEM_BYTES>>>(A0, A1, A2, Y);
}

// round 6
// speedup vs baseline: 1.7843x; 1.5744x over previous
#include <cuda_runtime.h>
#include <cuda_fp16.h>
#include <cstdint>

#define B_ 4
#define N_ 4096
#define F_ 64
#define BM 128
#define BK 32
#define NKT (N_ / BK)                  // 128
#define STAGES 3

// stage layout: A fp32 (3 chains x 128 rows x 160B padded) + T fp16 (3 x 64 x 64B)
#define A_ROW_B 160
#define A_CH_B (BM * A_ROW_B)          // 20480
#define A_BYTES (3 * A_CH_B)           // 61440
#define T_CH_B (F_ * 64)               // 4096
#define T_OFF A_BYTES
#define STAGE_BYTES (A_BYTES + 3 * T_CH_B)   // 73728
#define SMEM_BYTES (STAGES * STAGE_BYTES)    // 221184

// T scratch: g_T[c][b][n][k] = fp16_rne( (X[b] @ w_c)[k][n] )
__device__ __half g_T[3][B_][F_][N_];

// ---------------------------------------------------------------------------
__device__ __forceinline__ uint32_t smem_u32(const void* p) {
    uint32_t a;
    asm("{ .reg .u64 t; cvta.to.shared.u64 t, %1; cvt.u32.u64 %0, t; }"
        : "=r"(a) : "l"(p));
    return a;
}
__device__ __forceinline__ void ldsm4(uint32_t* r, uint32_t addr) {
    asm volatile("ldmatrix.sync.aligned.m8n8.x4.shared.b16 {%0,%1,%2,%3}, [%4];"
                 : "=r"(r[0]), "=r"(r[1]), "=r"(r[2]), "=r"(r[3]) : "r"(addr));
}
__device__ __forceinline__ uint32_t lds_cvt(uint32_t addr) {
    float x, y;
    asm volatile("ld.shared.v2.f32 {%0,%1}, [%2];" : "=f"(x), "=f"(y) : "r"(addr));
    __half2 h = __floats2half2_rn(x, y);
    return *(uint32_t*)&h;
}
__device__ __forceinline__ void mma16816(float* d, const uint32_t* a,
                                         uint32_t b0, uint32_t b1) {
    asm volatile("mma.sync.aligned.m16n8k16.row.col.f32.f16.f16.f32 "
                 "{%0,%1,%2,%3}, {%4,%5,%6,%7}, {%8,%9}, {%0,%1,%2,%3};"
                 : "+f"(d[0]), "+f"(d[1]), "+f"(d[2]), "+f"(d[3])
                 : "r"(a[0]), "r"(a[1]), "r"(a[2]), "r"(a[3]), "r"(b0), "r"(b1));
}
__device__ __forceinline__ uint32_t packh2(float x, float y) {
    __half2 h = __floats2half2_rn(x, y);
    return *(uint32_t*)&h;
}

// ---------------------------------------------------------------------------
// Kernel 1: g_T[c][b][g][m] = fp16( sum_f X[b][m][f] * w_c[f][g] )
// ---------------------------------------------------------------------------
__global__ void __launch_bounds__(256)
compute_T_kernel(const float* __restrict__ X,
                 const float* __restrict__ w0,
                 const float* __restrict__ w1,
                 const float* __restrict__ w2) {
    const int c = blockIdx.z;
    const int b = blockIdx.y;
    const int m0 = blockIdx.x * 64;
    const float* w = (c == 0) ? w0 : (c == 1) ? w1 : w2;

    __shared__ float sX[64 * 68];
    __shared__ float sW[64 * 68];

    const int tid = threadIdx.x;
    {
        const int q = tid & 15;
        const int r = tid >> 4;
        #pragma unroll
        for (int j = 0; j < 4; j++) {
            const int row = r + 16 * j;
            *(float4*)(sX + row * 68 + q * 4) =
                *(const float4*)(X + ((size_t)b * N_ + m0 + row) * F_ + q * 4);
            *(float4*)(sW + row * 68 + q * 4) =
                *(const float4*)(w + (size_t)row * F_ + q * 4);
        }
    }
    __syncthreads();

    const int row = tid >> 2;
    const int g0  = (tid & 3) * 16;

    float acc[16];
    #pragma unroll
    for (int i = 0; i < 16; i++) acc[i] = 0.f;

    #pragma unroll 8
    for (int f = 0; f < 64; f++) {
        const float x = sX[row * 68 + f];
        #pragma unroll
        for (int j = 0; j < 4; j++) {
            float4 wv = *(const float4*)(sW + f * 68 + g0 + j * 4);
            acc[j * 4 + 0] += x * wv.x;
            acc[j * 4 + 1] += x * wv.y;
            acc[j * 4 + 2] += x * wv.z;
            acc[j * 4 + 3] += x * wv.w;
        }
    }
    __syncthreads();

    #pragma unroll
    for (int j = 0; j < 4; j++)
        *(float4*)(sX + row * 68 + g0 + j * 4) =
            make_float4(acc[j*4+0], acc[j*4+1], acc[j*4+2], acc[j*4+3]);
    __syncthreads();

    const int g  = tid >> 2;
    const int ms = (tid & 3) * 16;
    uint32_t h[8];
    #pragma unroll
    for (int i = 0; i < 8; i++)
        h[i] = packh2(sX[(ms + 2*i) * 68 + g], sX[(ms + 2*i + 1) * 68 + g]);
    __half* out = &g_T[c][b][g][m0 + ms];
    ((uint4*)out)[0] = make_uint4(h[0], h[1], h[2], h[3]);
    ((uint4*)out)[1] = make_uint4(h[4], h[5], h[6], h[7]);
}

// ---------------------------------------------------------------------------
// Kernel 2: Y[b] = relu(A0@T0 + A1@T1 + A2@T2)
// grid (32, 4) = 128 CTAs, block 256 (8 warps, warp tile 16x64).
// Pure cp.async pipeline: A fp32 -> smem -> LDS.v2+cvt fragments; T fp16 ldmatrix.
// ---------------------------------------------------------------------------
__global__ void __launch_bounds__(256, 1)
gnn_main_kernel(const float* __restrict__ A0,
                const float* __restrict__ A1,
                const float* __restrict__ A2,
                float* __restrict__ Y) {
    extern __shared__ char smem[];
    const uint32_t sb = smem_u32(smem);
    const int tid = threadIdx.x;
    const int b = blockIdx.y;
    const int rowBase = blockIdx.x * BM;

    const float* Ap[3];
    Ap[0] = A0 + (size_t)b * N_ * N_;
    Ap[1] = A1 + (size_t)b * N_ * N_;
    Ap[2] = A2 + (size_t)b * N_ * N_;

    // A cp.async map: 12 x 16B per thread (384 rows x 8 chunks)
    const float* aSrc[12];
    uint32_t aDst[12];
    #pragma unroll
    for (int j = 0; j < 12; j++) {
        const int id  = tid + 256 * j;          // 0..3071
        const int row = id >> 3;                // 0..383 (chain*128 + r)
        const int ch  = id & 7;                 // 16B chunk within 128B row
        const int c   = row >> 7;
        const int r   = row & 127;
        aSrc[j] = Ap[c] + (size_t)(rowBase + r) * N_ + ch * 4;
        aDst[j] = (uint32_t)(row * A_ROW_B + ch * 16);
    }
    // T cp.async map: 3 x 16B per thread
    const __half* tSrc[3];
    uint32_t tDst[3];
    #pragma unroll
    for (int j = 0; j < 3; j++) {
        const int id = tid + 256 * j;           // 0..767
        const int c  = id >> 8;
        const int n  = (id >> 2) & 63;
        const int ch = id & 3;
        tSrc[j] = &g_T[c][b][n][0] + ch * 8;
        tDst[j] = (uint32_t)(T_OFF + c * T_CH_B + n * 64
                             + 16 * (ch ^ ((n >> 1) & 3)));
    }

    #define CP_STAGE(kt, slot) do {                                            \
        const uint32_t _so = sb + (uint32_t)(slot) * STAGE_BYTES;              \
        const int _k0 = (kt) * BK;                                             \
        _Pragma("unroll")                                                      \
        for (int j = 0; j < 12; j++)                                           \
            asm volatile("cp.async.cg.shared.global [%0], [%1], 16;"           \
                         :: "r"(_so + aDst[j]), "l"(aSrc[j] + _k0) : "memory");\
        _Pragma("unroll")                                                      \
        for (int j = 0; j < 3; j++)                                            \
            asm volatile("cp.async.cg.shared.global [%0], [%1], 16;"           \
                         :: "r"(_so + tDst[j]), "l"(tSrc[j] + _k0) : "memory");\
        asm volatile("cp.async.commit_group;" ::: "memory");                   \
    } while (0)

    // fragment geometry: 8 warps, warp tile 16(M) x 64(N)
    const int lane = tid & 31;
    const int warp = tid >> 5;
    const int mrow = lane >> 2;        // 0..7
    const int kp   = lane & 3;         // k-pair index
    const int row16 = lane & 15;
    const int cbit  = lane >> 4;
    const uint32_t swz = (uint32_t)((row16 >> 1) & 3);
    const uint32_t aFragOff = (uint32_t)((warp * 16 + mrow) * A_ROW_B + kp * 8);
    const uint32_t bRowOff  = (uint32_t)(T_OFF + row16 * 64);

    float acc[8][4];
    #pragma unroll
    for (int nt = 0; nt < 8; nt++)
        #pragma unroll
        for (int i = 0; i < 4; i++) acc[nt][i] = 0.f;

    // prologue: stages 0,1 in flight
    CP_STAGE(0, 0);
    CP_STAGE(1, 1);

    for (int s = 0; s < NKT; s++) {
        const int slot = s % 3;
        asm volatile("cp.async.wait_group 1;" ::: "memory");
        __syncthreads();

        const uint32_t stBase = sb + (uint32_t)slot * STAGE_BYTES;
        #pragma unroll
        for (int c = 0; c < 3; c++) {
            const uint32_t aCh = stBase + c * A_CH_B + aFragOff;
            const uint32_t bCh = stBase + c * T_CH_B + bRowOff;
            #pragma unroll
            for (int ks = 0; ks < 2; ks++) {
                // A fragment m16k16 (fp32 -> fp16 in-register)
                uint32_t a[4];
                const uint32_t ak = aCh + ks * 64;
                a[0] = lds_cvt(ak);
                a[1] = lds_cvt(ak + 8 * A_ROW_B);
                a[2] = lds_cvt(ak + 32);
                a[3] = lds_cvt(ak + 8 * A_ROW_B + 32);
                const uint32_t kch = 16u * ((uint32_t)((ks << 1) | cbit) ^ swz);
                #pragma unroll
                for (int nt = 0; nt < 4; nt++) {
                    uint32_t bb[4];
                    ldsm4(bb, bCh + nt * 1024 + kch);
                    mma16816(acc[2*nt],     a, bb[0], bb[2]);
                    mma16816(acc[2*nt + 1], a, bb[1], bb[3]);
                }
            }
        }

        if (s + 2 < NKT) {
            CP_STAGE(s + 2, (s + 2) % 3);
        } else {
            asm volatile("cp.async.commit_group;" ::: "memory");
        }
    }

    // epilogue: relu + store. warp rows = rowBase + warp*16 + (lane>>2) {,+8}
    #pragma unroll
    for (int nt = 0; nt < 8; nt++) {
        const int r0  = rowBase + warp * 16 + (lane >> 2);
        const int col = nt * 8 + (lane & 3) * 2;
        float2 v0 = make_float2(fmaxf(acc[nt][0], 0.f), fmaxf(acc[nt][1], 0.f));
        float2 v1 = make_float2(fmaxf(acc[nt][2], 0.f), fmaxf(acc[nt][3], 0.f));
        *(float2*)(Y + ((size_t)b * N_ + r0) * F_ + col)     = v0;
        *(float2*)(Y + ((size_t)b * N_ + r0 + 8) * F_ + col) = v1;
    }
}

// ---------------------------------------------------------------------------
extern "C" void kernel_launch(void* const* d_in, const int* in_sizes, int n_in,
                              void* d_out, int out_size) {
    (void)in_sizes; (void)n_in; (void)out_size;
    const float* X  = (const float*)d_in[0];
    const float* A0 = (const float*)d_in[1];
    const float* A1 = (const float*)d_in[2];
    const float* A2 = (const float*)d_in[3];
    const float* w0 = (const float*)d_in[4];
    const float* w1 = (const float*)d_in[5];
    const float* w2 = (const float*)d_in[6];
    float* Y = (float*)d_out;

    dim3 g1(N_ / 64, B_, 3);
    compute_T_kernel<<<g1, 256>>>(X, w0, w1, w2);

    cudaFuncSetAttribute(gnn_main_kernel,
                         cudaFuncAttributeMaxDynamicSharedMemorySize, SMEM_BYTES);
    dim3 g2(N_ / BM, B_);
    gnn_main_kernel<<<g2, 256, SMEM_BYTES>>>(A0, A1, A2, Y);
}